// round 11
// baseline (speedup 1.0000x reference)
#include <cuda_runtime.h>
#include <stdint.h>

// SpikeFP64Divider: gate-level FP64 restoring divider on rows of 64 {0,1} floats.
// Integer replica of the exact circuit semantics (13-bit modular exponent math,
// subnormal inputs treated as normals, mantissa-round carry-out structurally 0).
//
// R10: double-buffered cp.async pipeline. One warp per block, 4 tiles of 32
// rows per block, 2 smem stages (16KB each). Tile t+1's loads are issued
// before waiting on tile t (cp.async.wait_group 1), so DRAM reads stay in
// flight through the compute and store phases. Pack/divide/unpack identical
// to the verified R9 paths.

static __device__ __forceinline__ void cp_async16(uint32_t dst, const void* src) {
    asm volatile("cp.async.cg.shared.global [%0], [%1], 16;" :: "r"(dst), "l"(src));
}

__global__ __launch_bounds__(32) void spike_div_kernel(
    const float* __restrict__ A, const float* __restrict__ B, float* __restrict__ O)
{
    // [stage][array][row][chunk]; chunk swizzled by (row & 7). 32 KB static.
    __shared__ uint4 buf[2][2][32][16];

    const unsigned FULL = 0xFFFFFFFFu;
    const int lane = threadIdx.x;          // 32-thread block = 1 warp

    const long long blockRowBase = (long long)blockIdx.x * 128;   // 4 tiles x 32 rows
    const uint4* __restrict__ Ag0 = reinterpret_cast<const uint4*>(A) + blockRowBase * 16;
    const uint4* __restrict__ Bg0 = reinterpret_cast<const uint4*>(B) + blockRowBase * 16;

    // ---- issue one tile's loads (32 rows x 2 arrays) into a stage ----
    auto issue_tile = [&](int t, int stage) {
        const uint4* __restrict__ Ag = Ag0 + t * (32 * 16);
        const uint4* __restrict__ Bg = Bg0 + t * (32 * 16);
#pragma unroll
        for (int i = 0; i < 16; i++) {
            const int g = i * 32 + lane;   // chunk id: row g>>4, chunk g&15
            const int r = g >> 4;
            const int k = (g & 15) ^ (r & 7);
            cp_async16((uint32_t)__cvta_generic_to_shared(&buf[stage][0][r][k]), Ag + g);
            cp_async16((uint32_t)__cvta_generic_to_shared(&buf[stage][1][r][k]), Bg + g);
        }
        asm volatile("cp.async.commit_group;");
    };

    issue_tile(0, 0);

#pragma unroll
    for (int t = 0; t < 4; t++) {
        const int stage = t & 1;
        if (t + 1 < 4) {
            issue_tile(t + 1, (t + 1) & 1);
            asm volatile("cp.async.wait_group 1;" ::: "memory");   // tile t done
        } else {
            asm volatile("cp.async.wait_group 0;" ::: "memory");
        }
        __syncwarp();

        // ---- Pack: lane l packs row l of A and B from smem ----
        // Chunk k holds cols 4k..4k+3; col c -> bit 63-c; {0,1}f flag = bit 29.
        uint32_t hiA = 0u, loA = 0u, hiB = 0u, loB = 0u;
#pragma unroll
        for (int k = 0; k < 16; k++) {
            const int ks = k ^ (lane & 7);         // conflict-free per 8-lane phase
            const uint4 va = buf[stage][0][lane][ks];
            const uint32_t na = ((va.x >> 26) & 8u) | ((va.y >> 27) & 4u) |
                                ((va.z >> 28) & 2u) | ((va.w >> 29) & 1u);
            const uint4 vb = buf[stage][1][lane][ks];
            const uint32_t nb = ((vb.x >> 26) & 8u) | ((vb.y >> 27) & 4u) |
                                ((vb.z >> 28) & 2u) | ((vb.w >> 29) & 1u);
            if (k < 8) { hiA |= na << (28 - 4 * k);       hiB |= nb << (28 - 4 * k); }
            else       { loA |= na << (28 - 4 * (k - 8)); loB |= nb << (28 - 4 * (k - 8)); }
        }
        const uint64_t wa = ((uint64_t)hiA << 32) | (uint64_t)loA;
        const uint64_t wb = ((uint64_t)hiB << 32) | (uint64_t)loB;

        // ---- Circuit replica (one row per lane) ----
        const uint64_t M52 = 0x000FFFFFFFFFFFFFull;
        const uint32_t s_out = (uint32_t)((wa ^ wb) >> 63);
        const uint32_t ea = (uint32_t)(wa >> 52) & 0x7FFu;
        const uint32_t eb = (uint32_t)(wb >> 52) & 0x7FFu;
        const uint64_t ma = wa & M52;
        const uint64_t mb = wb & M52;

        const bool a_zero = (ea == 0u)     && (ma == 0ull);
        const bool b_zero = (eb == 0u)     && (mb == 0ull);
        const bool a_inf  = (ea == 0x7FFu) && (ma == 0ull);
        const bool b_inf  = (eb == 0x7FFu) && (mb == 0ull);
        const bool a_nan  = (ea == 0x7FFu) && (ma != 0ull);
        const bool b_nan  = (eb == 0x7FFu) && (mb != 0ull);

        const bool r_nan  = a_nan || b_nan || (a_zero && b_zero) || (a_inf && b_inf);
        const bool r_inf  = (!a_zero && b_zero) || (a_inf && !b_inf);
        const bool r_zero = (a_zero && !b_zero) || (!a_inf && b_inf);

        // 13-bit modular exponent arithmetic, as the ripple circuits do.
        int exp13 = ((int)ea - (int)eb + 1023) & 8191;

        // ---- Exact Q = floor(a * 2^56 / d) via 2 base-2^28 digits ----
        const uint64_t a = (1ull << 53) | (ma << 1);
        const uint64_t d = (1ull << 53) | (mb << 1);
        const int64_t  ds = (int64_t)d;
        const double inv = 1.0 / (double)d;

        int64_t q1 = (int64_t)((double)a * 0x1p28 * inv);
        int64_t r1 = (int64_t)((a << 28) - (uint64_t)q1 * d);
        if (r1 < 0)   { q1--; r1 += ds; }
        if (r1 < 0)   { q1--; r1 += ds; }
        if (r1 >= ds) { q1++; r1 -= ds; }

        int64_t q2 = (int64_t)((double)r1 * 0x1p28 * inv);
        int64_t r2 = (int64_t)(((uint64_t)r1 << 28) - (uint64_t)q2 * d);
        if (r2 < 0)   { q2--; r2 += ds; }
        if (r2 < 0)   { q2--; r2 += ds; }
        if (r2 >= ds) { q2++; r2 -= ds; }

        const uint64_t Q = ((uint64_t)q1 << 28) + (uint64_t)q2;  // 57-bit quotient
        const bool remnz = (r2 != 0);

        // Normalize + guard/round/sticky (Q bit 56 = first quotient bit).
        const uint32_t q0 = (uint32_t)(Q >> 56) & 1u;
        uint64_t mant;
        uint32_t rnd;
        bool sticky;
        if (q0) {
            mant   = (Q >> 4) & M52;
            rnd    = (uint32_t)(Q >> 3) & 1u;
            sticky = ((Q & 7ull) != 0ull) || remnz;
        } else {
            mant   = (Q >> 3) & M52;
            rnd    = (uint32_t)(Q >> 2) & 1u;
            sticky = ((Q & 3ull) != 0ull) || remnz;
            exp13  = (exp13 - 1) & 8191;
        }

        // RNE; circuit's 53-bit incrementer carry-out is structurally 0:
        // mantissa overflow wraps to 0 WITHOUT exponent bump (mask only).
        const uint32_t lsb = (uint32_t)mant & 1u;
        const uint32_t rup = (rnd && (sticky || lsb)) ? 1u : 0u;
        mant = (mant + (uint64_t)rup) & M52;

        const uint32_t exp_field = (uint32_t)exp13 & 0x7FFu;
        const bool ovf = ((exp13 >> 11) & 3) != 0;
        const bool unf = (((exp13 >> 12) & 1) != 0) || (exp13 == 0);

        const uint64_t sbit = (uint64_t)s_out << 63;
        uint64_t out;
        if (r_nan)       out = sbit | (0x7FFull << 52) | (1ull << 51);
        else if (r_inf)  out = sbit | (0x7FFull << 52);
        else if (r_zero) out = sbit;
        else if (ovf)    out = sbit | (0x7FFull << 52);
        else if (unf)    out = sbit;
        else             out = sbit | ((uint64_t)exp_field << 52) | mant;

        // ---- Unpack: shuffle hi/lo from owner lane (lane r owns row r),
        // STG.128 float4. float4 i = k*32+lane: row 2k+(lane>>4), nib lane&15.
        const uint32_t hi_o = (uint32_t)(out >> 32);   // cols  0..31
        const uint32_t lo_o = (uint32_t)out;           // cols 32..63
        float4* __restrict__ O4 =
            reinterpret_cast<float4*>(O + (blockRowBase + t * 32) * 64);
        const int hsel = (lane >> 4) & 1;
        const bool use_lo = (lane & 8) != 0;
        const int nsh = 28 - 4 * (lane & 7);
#pragma unroll
        for (int k = 0; k < 16; k++) {
            const int src = 2 * k + hsel;              // row index = owner lane
            const uint32_t wh = __shfl_sync(FULL, hi_o, src);
            const uint32_t wl = __shfl_sync(FULL, lo_o, src);
            const uint32_t word = use_lo ? wl : wh;
            const uint32_t nib = (word >> nsh) & 0xFu;
            float4 v;
            v.x = __uint_as_float((nib & 8u) ? 0x3F800000u : 0u);
            v.y = __uint_as_float((nib & 4u) ? 0x3F800000u : 0u);
            v.z = __uint_as_float((nib & 2u) ? 0x3F800000u : 0u);
            v.w = __uint_as_float((nib & 1u) ? 0x3F800000u : 0u);
            O4[k * 32 + lane] = v;
        }
        __syncwarp();   // stage reuse guard (tile t+2 overwrites this stage)
    }
}

extern "C" void kernel_launch(void* const* d_in, const int* in_sizes, int n_in,
                              void* d_out, int out_size) {
    const float* A = (const float*)d_in[0];
    const float* B = (const float*)d_in[1];
    float* O = (float*)d_out;
    const int rows = in_sizes[0] / 64;       // 131072
    const int grid = rows / 128;             // 1024 blocks: 1 warp, 4 tiles x 32 rows
    spike_div_kernel<<<grid, 32>>>(A, B, O);
}